// round 11
// baseline (speedup 1.0000x reference)
#include <cuda_runtime.h>
#include <cuda_bf16.h>
#include <cstdint>

// FineMatching (P=512, R=S=128, K=3, THRESH=0.05, OR-combine, conditional).
// R11: R9 structure (2-CTA clusters, half-proposal/CTA, cp.async fill,
// DSMEM col-partial exchange) + TMA BULK STORES: P3 stages results in a
// double-buffered smem area and drains via cp.async.bulk (UTMASTG) --
// no STG instructions, no L1tex store wavefronts, async smem->L2.

#define PP 512
#define NT 256
#define XTHRESH (-2.99573227355f)   // ln(0.05)

// dynamic smem layout (floats)
#define TILE_F   0                  // [64*132] raw x, pitch 132
#define OBUF_F   8448               // float4[2][512]: per-buf 256 score + 256 corr
#define CP1_F    12544              // [128]
#define CP2_F    12672              // [128]
#define CP3_F    12800              // [128]
#define COLT_F   12928              // [128]
#define RINF_F   13056              // float2[64]
#define SMEM_F   13184              // total floats -> 52736 bytes

struct Top3 { float v1, v2, v3; };

__device__ __forceinline__ void ins3(Top3& t, float v) {
    float t1 = fminf(t.v1, v);
    float t2 = fminf(t.v2, v);
    t.v1 = fmaxf(t.v1, v);
    t.v2 = fmaxf(t.v2, t1);
    t.v3 = fmaxf(t.v3, t2);
}

__device__ __forceinline__ void merge(Top3& a, const Top3& b) {
    ins3(a, b.v1);
    ins3(a, b.v2);
    ins3(a, b.v3);
}

__device__ __forceinline__ void merge_xor1(Top3& t) {
    Top3 b;
    b.v1 = __shfl_xor_sync(0xffffffffu, t.v1, 1);
    b.v2 = __shfl_xor_sync(0xffffffffu, t.v2, 1);
    b.v3 = __shfl_xor_sync(0xffffffffu, t.v3, 1);
    merge(t, b);
}

#define T3INIT {-1e30f, -1e30f, -1e30f}

__device__ __forceinline__ float ld_peer_f32(uint32_t local_saddr, uint32_t peer_rank) {
    uint32_t ra;
    float v;
    asm volatile("mapa.shared::cluster.u32 %0, %1, %2;"
                 : "=r"(ra) : "r"(local_saddr), "r"(peer_rank));
    asm volatile("ld.shared::cluster.f32 %0, [%1];" : "=f"(v) : "r"(ra));
    return v;
}

__device__ __forceinline__ void bulk_store(void* dst, uint32_t src_saddr, int bytes) {
    asm volatile("cp.async.bulk.global.shared::cta.bulk_group [%0], [%1], %2;"
                 :: "l"(dst), "r"(src_saddr), "r"(bytes) : "memory");
}

__global__ __launch_bounds__(NT, 4) __cluster_dims__(2, 1, 1)
void fine_matching_kernel(
    const float4* __restrict__ msm4,        // [P,R,S] as float4 (raw log-scores)
    const unsigned int* __restrict__ refm,  // [P,R] 32-bit bool
    const uint4* __restrict__ srcm4,        // [P,S] 32-bit bool as uint4
    const float* __restrict__ ncs,          // [P]
    float4* __restrict__ out4,              // [score | corr] as float4
    int write_corr)
{
    extern __shared__ __align__(16) float sh[];
    float*  tile    = sh + TILE_F;                  // [64*132]
    float4* obuf    = (float4*)(sh + OBUF_F);       // [2][512]
    float*  cp1     = sh + CP1_F;
    float*  cp2     = sh + CP2_F;
    float*  cp3     = sh + CP3_F;
    float*  colT    = sh + COLT_F;
    float2* rowInfo = (float2*)(sh + RINF_F);       // (rowTx, refmaskF)

    const int bid  = blockIdx.x;
    const int p    = bid >> 1;
    const int half = bid & 1;                        // == cluster rank
    const uint32_t peer = (uint32_t)(half ^ 1);
    const int tid  = threadIdx.x;
    const int lane = tid & 31;

    // ---- P0/P1: masks; half-tile fill via cp.async (8 x 16B in flight)
    if (tid < 64)
        rowInfo[tid].y = (refm[p * 128 + half * 64 + tid] != 0u) ? 1.0f : 0.0f;

    {
        const float4* g = msm4 + p * 4096 + half * 2048 + tid;
        uint32_t sp = (uint32_t)__cvta_generic_to_shared(
            (float4*)tile + (tid >> 5) * 33 + lane);
        #pragma unroll
        for (int k = 0; k < 8; k++) {
            asm volatile("cp.async.cg.shared.global [%0], [%1], 16;"
                         :: "r"(sp + k * (8 * 33 * 16)), "l"(g + k * NT));
        }
        asm volatile("cp.async.commit_group;");
        asm volatile("cp.async.wait_group 0;" ::: "memory");
    }
    __syncthreads();

    // ---- P2: local scans (threads 0..127 cols, 128..255 rows)
    if (tid < 128) {
        // 1 thread per column, 64 rows, 4 interleaved accumulators
        const float* base = tile + tid;
        Top3 t0 = T3INIT, t1 = T3INIT, t2 = T3INIT, t3 = T3INIT;
        #pragma unroll
        for (int j = 0; j < 16; j++) {
            ins3(t0, base[(4 * j + 0) * 132]);
            ins3(t1, base[(4 * j + 1) * 132]);
            ins3(t2, base[(4 * j + 2) * 132]);
            ins3(t3, base[(4 * j + 3) * 132]);
        }
        merge(t0, t1);
        merge(t2, t3);
        merge(t0, t2);
        cp1[tid] = t0.v1;
        cp2[tid] = t0.v2;
        cp3[tid] = t0.v3;
    } else {
        // 2 threads per row (64 rows), LDS.128; half1 f4 20..31 then 16..19
        const int u  = tid - 128;
        const int r  = u >> 1;
        const int hf = u & 1;
        Top3 t0 = T3INIT, t1 = T3INIT, t2 = T3INIT, t3 = T3INIT;
        const float4* ra = (const float4*)tile + r * 33 + (hf ? 20 : 0);
        #pragma unroll
        for (int j = 0; j < 12; j++) {
            float4 v = ra[j];
            ins3(t0, v.x);
            ins3(t1, v.y);
            ins3(t2, v.z);
            ins3(t3, v.w);
        }
        const float4* rb = (const float4*)tile + r * 33 + (hf ? 16 : 12);
        #pragma unroll
        for (int j = 0; j < 4; j++) {
            float4 v = rb[j];
            ins3(t0, v.x);
            ins3(t1, v.y);
            ins3(t2, v.z);
            ins3(t3, v.w);
        }
        merge(t0, t1);
        merge(t2, t3);
        merge(t0, t2);
        merge_xor1(t0);
        if (!hf) rowInfo[r].x = t0.v3;
    }
    __syncthreads();

    // ---- Exchange col partials with cluster peer, merge
    asm volatile("barrier.cluster.arrive.aligned;" ::: "memory");
    asm volatile("barrier.cluster.wait.aligned;" ::: "memory");

    if (tid < 128) {
        Top3 t;
        t.v1 = cp1[tid];
        t.v2 = cp2[tid];
        t.v3 = cp3[tid];
        uint32_t a1 = (uint32_t)__cvta_generic_to_shared(cp1 + tid);
        uint32_t a2 = (uint32_t)__cvta_generic_to_shared(cp2 + tid);
        uint32_t a3 = (uint32_t)__cvta_generic_to_shared(cp3 + tid);
        ins3(t, ld_peer_f32(a1, peer));
        ins3(t, ld_peer_f32(a2, peer));
        ins3(t, ld_peer_f32(a3, peer));
        colT[tid] = t.v3;
    }
    __syncthreads();
    // done touching peer smem after this point; arrive now, wait at kernel end
    asm volatile("barrier.cluster.arrive.aligned;" ::: "memory");

    // ---- P3: compute into staging smem; drain via TMA bulk stores
    const float scale = 0.5f * __ldg(ncs + p);
    const float4 cT = *(const float4*)(colT + 4 * lane);
    const uint4 smv = srcm4[p * 32 + lane];
    const float m0 = (smv.x != 0u) ? 1.f : 0.f;
    const float m1 = (smv.y != 0u) ? 1.f : 0.f;
    const float m2 = (smv.z != 0u) ? 1.f : 0.f;
    const float m3 = (smv.w != 0u) ? 1.f : 0.f;

    const float4* tp  = (const float4*)tile + (tid >> 5) * 33 + lane;
    const float2* rip = rowInfo + (tid >> 5);
    float4* sco = out4 + (size_t)p * 4096 + half * 2048;
    float4* cor = sco + (size_t)PP * 4096;

    const uint32_t obuf_s = (uint32_t)__cvta_generic_to_shared(obuf);

    #pragma unroll
    for (int k = 0; k < 8; k++) {
        const int buf = k & 1;

        // buffer reuse gate: chunk k-2's bulk reads must be done
        if (k >= 2) {
            if (tid == 0)
                asm volatile("cp.async.bulk.wait_group.read 1;" ::: "memory");
            __syncthreads();
        }

        float2 ri = rip[8 * k];             // warp-uniform (rowTx, refmaskF)
        float4 x  = tp[k * 8 * 33];

        bool ax = x.x >= ri.x, bx = x.x >= cT.x;
        bool ay = x.y >= ri.x, by = x.y >= cT.y;
        bool az = x.z >= ri.x, bz = x.z >= cT.z;
        bool aw = x.w >= ri.x, bw = x.w >= cT.w;

        float svx = scale * __expf(x.x), svy = scale * __expf(x.y);
        float svz = scale * __expf(x.z), svw = scale * __expf(x.w);

        float4 s4;
        s4.x = (ax ? svx : 0.f) + (bx ? svx : 0.f);
        s4.y = (ay ? svy : 0.f) + (by ? svy : 0.f);
        s4.z = (az ? svz : 0.f) + (bz ? svz : 0.f);
        s4.w = (aw ? svw : 0.f) + (bw ? svw : 0.f);
        obuf[buf * 512 + tid] = s4;

        if (write_corr) {
            float4 c4;
            c4.x = ((ax || bx) && x.x > XTHRESH) ? ri.y * m0 : 0.f;
            c4.y = ((ay || by) && x.y > XTHRESH) ? ri.y * m1 : 0.f;
            c4.z = ((az || bz) && x.z > XTHRESH) ? ri.y * m2 : 0.f;
            c4.w = ((aw || bw) && x.w > XTHRESH) ? ri.y * m3 : 0.f;
            obuf[buf * 512 + 256 + tid] = c4;
        }
        __syncthreads();

        if (tid == 0) {
            asm volatile("fence.proxy.async.shared::cta;" ::: "memory");
            bulk_store(sco + k * 256, obuf_s + buf * 8192, 4096);
            if (write_corr)
                bulk_store(cor + k * 256, obuf_s + buf * 8192 + 4096, 4096);
            asm volatile("cp.async.bulk.commit_group;");
        }
    }

    // drain all bulk stores before exit
    if (tid == 0)
        asm volatile("cp.async.bulk.wait_group 0;" ::: "memory");

    // don't exit while peer may still read my cp arrays
    asm volatile("barrier.cluster.wait.aligned;" ::: "memory");
}

extern "C" void kernel_launch(void* const* d_in, const int* in_sizes, int n_in,
                              void* d_out, int out_size) {
    const float4* msm4       = (const float4*)d_in[0];
    const unsigned int* refm = (const unsigned int*)d_in[1];
    const uint4* srcm4       = (const uint4*)d_in[2];
    const float* ncs         = (const float*)d_in[3];
    float4* out4             = (float4*)d_out;

    const int prs = PP * 128 * 128;
    int write_corr = (out_size >= 2 * prs) ? 1 : 0;

    size_t smem = (size_t)SMEM_F * sizeof(float);   // 52736 bytes
    cudaFuncSetAttribute(fine_matching_kernel,
                         cudaFuncAttributeMaxDynamicSharedMemorySize, (int)smem);

    fine_matching_kernel<<<2 * PP, NT, smem>>>(msm4, refm, srcm4, ncs, out4,
                                               write_corr);
}

// round 12
// speedup vs baseline: 1.1792x; 1.1792x over previous
#include <cuda_runtime.h>
#include <cuda_bf16.h>
#include <cstdint>

// FineMatching (P=512, R=S=128, K=3, THRESH=0.05, OR-combine, conditional).
// R12: R9 structure + column partial top-3 fused into P1's load shadow.
//   Load mapping: thread (warp w, lane l) iter k holds row w+8k, cols 4l..4l+3
//   -> 4 register Top3 accumulators build per-thread column partials during
//   the global-load latency. P2 column work becomes an 8-way partial merge
//   (24 LDS + ~105 FMNMX) instead of 64 scalar LDS + 320 FMNMX.
//   Rows: R9's 2-thr/row LDS.128 scan (overlaps cluster barrier wait).
//   2-CTA clusters, DSMEM col exchange, x-domain thresholds, __stcs stores.

#define PP 512
#define NT 256
#define XTHRESH (-2.99573227355f)   // ln(0.05)

struct Top3 { float v1, v2, v3; };

__device__ __forceinline__ void ins3(Top3& t, float v) {
    float t1 = fminf(t.v1, v);
    float t2 = fminf(t.v2, v);
    t.v1 = fmaxf(t.v1, v);
    t.v2 = fmaxf(t.v2, t1);
    t.v3 = fmaxf(t.v3, t2);
}

__device__ __forceinline__ void merge(Top3& a, const Top3& b) {
    ins3(a, b.v1);
    ins3(a, b.v2);
    ins3(a, b.v3);
}

__device__ __forceinline__ void merge_xor1(Top3& t) {
    Top3 b;
    b.v1 = __shfl_xor_sync(0xffffffffu, t.v1, 1);
    b.v2 = __shfl_xor_sync(0xffffffffu, t.v2, 1);
    b.v3 = __shfl_xor_sync(0xffffffffu, t.v3, 1);
    merge(t, b);
}

#define T3INIT {-1e30f, -1e30f, -1e30f}

__device__ __forceinline__ float ld_peer_f32(uint32_t local_saddr, uint32_t peer_rank) {
    uint32_t ra;
    float v;
    asm volatile("mapa.shared::cluster.u32 %0, %1, %2;"
                 : "=r"(ra) : "r"(local_saddr), "r"(peer_rank));
    asm volatile("ld.shared::cluster.f32 %0, [%1];" : "=f"(v) : "r"(ra));
    return v;
}

__global__ __launch_bounds__(NT, 4) __cluster_dims__(2, 1, 1)
void fine_matching_kernel(
    const float4* __restrict__ msm4,        // [P,R,S] as float4 (raw log-scores)
    const unsigned int* __restrict__ refm,  // [P,R] 32-bit bool
    const uint4* __restrict__ srcm4,        // [P,S] 32-bit bool as uint4
    const float* __restrict__ ncs,          // [P]
    float4* __restrict__ out4,              // [score | corr] as float4
    int write_corr)
{
    __shared__ __align__(16) float tile[64 * 132];   // half-tile raw x, pitch 132
    // per-(warp,col) column partials, addr = w*128 + j*32 + lane (banks = lane)
    __shared__ float cpt1[1024], cpt2[1024], cpt3[1024];
    __shared__ float cp1[128], cp2[128], cp3[128];   // CTA-merged col partials
    __shared__ __align__(16) float colT[128];        // final col thresholds
    __shared__ float2 rowInfo[64];                   // (rowTx, refmaskF)

    const int bid  = blockIdx.x;
    const int p    = bid >> 1;
    const int half = bid & 1;                        // == cluster rank
    const uint32_t peer = (uint32_t)(half ^ 1);
    const int tid  = threadIdx.x;
    const int lane = tid & 31;
    const int wid  = tid >> 5;

    // ---- P0: ref mask
    if (tid < 64)
        rowInfo[tid].y = (refm[p * 128 + half * 64 + tid] != 0u) ? 1.0f : 0.0f;

    // ---- P1: tile fill + column partial top-3 in the load shadow
    {
        const float4* g = msm4 + p * 4096 + half * 2048 + tid;
        float4* tf4 = (float4*)tile + wid * 33 + lane;
        Top3 c0 = T3INIT, c1 = T3INIT, c2 = T3INIT, c3 = T3INIT;
        float4 cur = g[0];
        #pragma unroll
        for (int k = 0; k < 8; k++) {
            float4 nxt;
            if (k < 7) nxt = g[(k + 1) * NT];
            tf4[k * 8 * 33] = cur;               // STS.128, banks 4l (clean)
            ins3(c0, cur.x);
            ins3(c1, cur.y);
            ins3(c2, cur.z);
            ins3(c3, cur.w);
            cur = nxt;
        }
        // store partials: col 4*lane+j -> addr wid*128 + j*32 + lane
        float* b = cpt1 + wid * 128 + lane;
        b[0] = c0.v1;  b[32] = c1.v1;  b[64] = c2.v1;  b[96] = c3.v1;
        b = cpt2 + wid * 128 + lane;
        b[0] = c0.v2;  b[32] = c1.v2;  b[64] = c2.v2;  b[96] = c3.v2;
        b = cpt3 + wid * 128 + lane;
        b[0] = c0.v3;  b[32] = c1.v3;  b[64] = c2.v3;  b[96] = c3.v3;
    }
    __syncthreads();

    // ---- P2: threads 0..127 merge col partials; 128..255 scan rows
    int mycol = -1;
    Top3 myct = T3INIT;
    if (tid < 128) {
        // thread handles col c = 4*lane + wid_sub; reads addr w*128+wid_sub*32+lane
        const int j = tid >> 5;                  // 0..3
        mycol = 4 * lane + j;
        const float* q1 = cpt1 + j * 32 + lane;  // + w*128, banks = lane (clean)
        const float* q2 = cpt2 + j * 32 + lane;
        const float* q3 = cpt3 + j * 32 + lane;
        myct.v1 = q1[0];
        myct.v2 = q2[0];
        myct.v3 = q3[0];
        #pragma unroll
        for (int w = 1; w < 8; w++) {
            ins3(myct, q1[w * 128]);
            ins3(myct, q2[w * 128]);
            ins3(myct, q3[w * 128]);
        }
        cp1[mycol] = myct.v1;
        cp2[mycol] = myct.v2;
        cp3[mycol] = myct.v3;
    } else {
        // rows: 2 threads/row (64 rows), LDS.128; half1 f4 20..31 then 16..19
        const int u  = tid - 128;
        const int r  = u >> 1;
        const int hf = u & 1;
        Top3 t0 = T3INIT, t1 = T3INIT, t2 = T3INIT, t3 = T3INIT;
        const float4* ra = (const float4*)tile + r * 33 + (hf ? 20 : 0);
        #pragma unroll
        for (int jj = 0; jj < 12; jj++) {
            float4 v = ra[jj];
            ins3(t0, v.x);
            ins3(t1, v.y);
            ins3(t2, v.z);
            ins3(t3, v.w);
        }
        const float4* rb = (const float4*)tile + r * 33 + (hf ? 16 : 12);
        #pragma unroll
        for (int jj = 0; jj < 4; jj++) {
            float4 v = rb[jj];
            ins3(t0, v.x);
            ins3(t1, v.y);
            ins3(t2, v.z);
            ins3(t3, v.w);
        }
        merge(t0, t1);
        merge(t2, t3);
        merge(t0, t2);
        merge_xor1(t0);
        if (!hf) rowInfo[r].x = t0.v3;
    }
    __syncthreads();

    // ---- Exchange col partials with cluster peer, merge
    asm volatile("barrier.cluster.arrive.aligned;" ::: "memory");
    asm volatile("barrier.cluster.wait.aligned;" ::: "memory");

    if (tid < 128) {
        uint32_t a1 = (uint32_t)__cvta_generic_to_shared(cp1 + mycol);
        uint32_t a2 = (uint32_t)__cvta_generic_to_shared(cp2 + mycol);
        uint32_t a3 = (uint32_t)__cvta_generic_to_shared(cp3 + mycol);
        ins3(myct, ld_peer_f32(a1, peer));
        ins3(myct, ld_peer_f32(a2, peer));
        ins3(myct, ld_peer_f32(a3, peer));
        colT[mycol] = myct.v3;
    }
    __syncthreads();
    // done touching peer smem after this point; arrive now, wait at kernel end
    asm volatile("barrier.cluster.arrive.aligned;" ::: "memory");

    // ---- P3: dense output for my 64 rows; __stcs streaming stores
    const float scale = 0.5f * __ldg(ncs + p);
    const float4 cT = *(const float4*)(colT + 4 * lane);
    const uint4 smv = srcm4[p * 32 + lane];
    const float m0 = (smv.x != 0u) ? 1.f : 0.f;
    const float m1 = (smv.y != 0u) ? 1.f : 0.f;
    const float m2 = (smv.z != 0u) ? 1.f : 0.f;
    const float m3 = (smv.w != 0u) ? 1.f : 0.f;

    const float4* tp  = (const float4*)tile + wid * 33 + lane;
    const float2* rip = rowInfo + wid;
    float4* sco = out4 + (size_t)p * 4096 + half * 2048 + tid;
    float4* cor = sco + (size_t)PP * 4096;

    if (write_corr) {
        #pragma unroll
        for (int k = 0; k < 8; k++) {
            float2 ri = rip[8 * k];             // warp-uniform (rowTx, refmaskF)
            float4 x  = tp[k * 8 * 33];

            bool ax = x.x >= ri.x, bx = x.x >= cT.x;
            bool ay = x.y >= ri.x, by = x.y >= cT.y;
            bool az = x.z >= ri.x, bz = x.z >= cT.z;
            bool aw = x.w >= ri.x, bw = x.w >= cT.w;

            float svx = scale * __expf(x.x), svy = scale * __expf(x.y);
            float svz = scale * __expf(x.z), svw = scale * __expf(x.w);

            float4 s4;
            s4.x = (ax ? svx : 0.f) + (bx ? svx : 0.f);
            s4.y = (ay ? svy : 0.f) + (by ? svy : 0.f);
            s4.z = (az ? svz : 0.f) + (bz ? svz : 0.f);
            s4.w = (aw ? svw : 0.f) + (bw ? svw : 0.f);
            __stcs(sco + k * NT, s4);

            float4 c4;
            c4.x = ((ax || bx) && x.x > XTHRESH) ? ri.y * m0 : 0.f;
            c4.y = ((ay || by) && x.y > XTHRESH) ? ri.y * m1 : 0.f;
            c4.z = ((az || bz) && x.z > XTHRESH) ? ri.y * m2 : 0.f;
            c4.w = ((aw || bw) && x.w > XTHRESH) ? ri.y * m3 : 0.f;
            __stcs(cor + k * NT, c4);
        }
    } else {
        #pragma unroll
        for (int k = 0; k < 8; k++) {
            float2 ri = rip[8 * k];
            float4 x  = tp[k * 8 * 33];
            bool ax = x.x >= ri.x, bx = x.x >= cT.x;
            bool ay = x.y >= ri.x, by = x.y >= cT.y;
            bool az = x.z >= ri.x, bz = x.z >= cT.z;
            bool aw = x.w >= ri.x, bw = x.w >= cT.w;
            float svx = scale * __expf(x.x), svy = scale * __expf(x.y);
            float svz = scale * __expf(x.z), svw = scale * __expf(x.w);
            float4 s4;
            s4.x = (ax ? svx : 0.f) + (bx ? svx : 0.f);
            s4.y = (ay ? svy : 0.f) + (by ? svy : 0.f);
            s4.z = (az ? svz : 0.f) + (bz ? svz : 0.f);
            s4.w = (aw ? svw : 0.f) + (bw ? svw : 0.f);
            __stcs(sco + k * NT, s4);
        }
    }

    // don't exit while peer may still read my cp arrays
    asm volatile("barrier.cluster.wait.aligned;" ::: "memory");
}

extern "C" void kernel_launch(void* const* d_in, const int* in_sizes, int n_in,
                              void* d_out, int out_size) {
    const float4* msm4       = (const float4*)d_in[0];
    const unsigned int* refm = (const unsigned int*)d_in[1];
    const uint4* srcm4       = (const uint4*)d_in[2];
    const float* ncs         = (const float*)d_in[3];
    float4* out4             = (float4*)d_out;

    const int prs = PP * 128 * 128;
    int write_corr = (out_size >= 2 * prs) ? 1 : 0;

    fine_matching_kernel<<<2 * PP, NT>>>(msm4, refm, srcm4, ncs, out4,
                                         write_corr);
}

// round 13
// speedup vs baseline: 1.1936x; 1.0122x over previous
#include <cuda_runtime.h>
#include <cuda_bf16.h>
#include <cstdint>

// FineMatching (P=512, R=S=128, K=3, THRESH=0.05, OR-combine, conditional).
// R13 = R9 verbatim (best measured: 19.0us). 2-CTA clusters, one
// half-proposal (64 rows x 128 cols) per CTA:
//   grid 1024 x 256 thr, ~36KB smem -> 6 CTAs/SM; tail granule halved.
//   Rows: local top-3. Cols: 64-row partial top-3, exchanged with cluster
//   peer via DSMEM (mapa + ld.shared::cluster), merged locally.
//   Thresholds on raw x (exp monotone); score uses __expf; __stcs stores.
// All alternatives (ALU cuts, TMA stores, shadow fusion, splits, store
// policies, higher occupancy) measured slower across R4-R12.

#define PP 512
#define NT 256
#define XTHRESH (-2.99573227355f)   // ln(0.05)

struct Top3 { float v1, v2, v3; };

__device__ __forceinline__ void ins3(Top3& t, float v) {
    float t1 = fminf(t.v1, v);
    float t2 = fminf(t.v2, v);
    t.v1 = fmaxf(t.v1, v);
    t.v2 = fmaxf(t.v2, t1);
    t.v3 = fmaxf(t.v3, t2);
}

__device__ __forceinline__ void merge(Top3& a, const Top3& b) {
    ins3(a, b.v1);
    ins3(a, b.v2);
    ins3(a, b.v3);
}

__device__ __forceinline__ void merge_xor1(Top3& t) {
    Top3 b;
    b.v1 = __shfl_xor_sync(0xffffffffu, t.v1, 1);
    b.v2 = __shfl_xor_sync(0xffffffffu, t.v2, 1);
    b.v3 = __shfl_xor_sync(0xffffffffu, t.v3, 1);
    merge(t, b);
}

#define T3INIT {-1e30f, -1e30f, -1e30f}

__device__ __forceinline__ float ld_peer_f32(uint32_t local_saddr, uint32_t peer_rank) {
    uint32_t ra;
    float v;
    asm volatile("mapa.shared::cluster.u32 %0, %1, %2;"
                 : "=r"(ra) : "r"(local_saddr), "r"(peer_rank));
    asm volatile("ld.shared::cluster.f32 %0, [%1];" : "=f"(v) : "r"(ra));
    return v;
}

__global__ __launch_bounds__(NT, 6) __cluster_dims__(2, 1, 1)
void fine_matching_kernel(
    const float4* __restrict__ msm4,        // [P,R,S] as float4 (raw log-scores)
    const unsigned int* __restrict__ refm,  // [P,R] 32-bit bool
    const uint4* __restrict__ srcm4,        // [P,S] 32-bit bool as uint4
    const float* __restrict__ ncs,          // [P]
    float4* __restrict__ out4,              // [score | corr] as float4
    int write_corr)
{
    __shared__ __align__(16) float tile[64 * 132];   // half-tile, pitch 132
    __shared__ float cp1[128], cp2[128], cp3[128];   // my col partial top-3
    __shared__ __align__(16) float colT[128];        // merged col thresholds
    __shared__ float2 rowInfo[64];                   // (rowTx, refmaskF)

    const int bid  = blockIdx.x;
    const int p    = bid >> 1;
    const int half = bid & 1;                        // == cluster rank
    const uint32_t peer = (uint32_t)(half ^ 1);
    const int tid  = threadIdx.x;
    const int lane = tid & 31;

    // ---- P0/P1: masks; half-tile fill via cp.async (8 x 16B in flight)
    if (tid < 64)
        rowInfo[tid].y = (refm[p * 128 + half * 64 + tid] != 0u) ? 1.0f : 0.0f;

    {
        const float4* g = msm4 + p * 4096 + half * 2048 + tid;
        uint32_t sp = (uint32_t)__cvta_generic_to_shared(
            (float4*)tile + (tid >> 5) * 33 + lane);
        #pragma unroll
        for (int k = 0; k < 8; k++) {
            asm volatile("cp.async.cg.shared.global [%0], [%1], 16;"
                         :: "r"(sp + k * (8 * 33 * 16)), "l"(g + k * NT));
        }
        asm volatile("cp.async.commit_group;");
        asm volatile("cp.async.wait_group 0;" ::: "memory");
    }
    __syncthreads();

    // ---- P2: local scans (threads 0..127 cols, 128..255 rows)
    if (tid < 128) {
        // 1 thread per column, 64 rows, 4 interleaved accumulators
        const float* base = tile + tid;
        Top3 t0 = T3INIT, t1 = T3INIT, t2 = T3INIT, t3 = T3INIT;
        #pragma unroll
        for (int j = 0; j < 16; j++) {
            ins3(t0, base[(4 * j + 0) * 132]);
            ins3(t1, base[(4 * j + 1) * 132]);
            ins3(t2, base[(4 * j + 2) * 132]);
            ins3(t3, base[(4 * j + 3) * 132]);
        }
        merge(t0, t1);
        merge(t2, t3);
        merge(t0, t2);
        cp1[tid] = t0.v1;
        cp2[tid] = t0.v2;
        cp3[tid] = t0.v3;
    } else {
        // 2 threads per row (64 rows), LDS.128; half1 f4 20..31 then 16..19
        const int u  = tid - 128;
        const int r  = u >> 1;
        const int hf = u & 1;
        Top3 t0 = T3INIT, t1 = T3INIT, t2 = T3INIT, t3 = T3INIT;
        const float4* ra = (const float4*)tile + r * 33 + (hf ? 20 : 0);
        #pragma unroll
        for (int j = 0; j < 12; j++) {
            float4 v = ra[j];
            ins3(t0, v.x);
            ins3(t1, v.y);
            ins3(t2, v.z);
            ins3(t3, v.w);
        }
        const float4* rb = (const float4*)tile + r * 33 + (hf ? 16 : 12);
        #pragma unroll
        for (int j = 0; j < 4; j++) {
            float4 v = rb[j];
            ins3(t0, v.x);
            ins3(t1, v.y);
            ins3(t2, v.z);
            ins3(t3, v.w);
        }
        merge(t0, t1);
        merge(t2, t3);
        merge(t0, t2);
        merge_xor1(t0);
        if (!hf) rowInfo[r].x = t0.v3;
    }
    __syncthreads();

    // ---- Exchange col partials with cluster peer, merge
    asm volatile("barrier.cluster.arrive.aligned;" ::: "memory");
    asm volatile("barrier.cluster.wait.aligned;" ::: "memory");

    if (tid < 128) {
        Top3 t;
        t.v1 = cp1[tid];
        t.v2 = cp2[tid];
        t.v3 = cp3[tid];
        uint32_t a1 = (uint32_t)__cvta_generic_to_shared(cp1 + tid);
        uint32_t a2 = (uint32_t)__cvta_generic_to_shared(cp2 + tid);
        uint32_t a3 = (uint32_t)__cvta_generic_to_shared(cp3 + tid);
        ins3(t, ld_peer_f32(a1, peer));
        ins3(t, ld_peer_f32(a2, peer));
        ins3(t, ld_peer_f32(a3, peer));
        colT[tid] = t.v3;
    }
    __syncthreads();
    // done touching peer smem after this point; arrive now, wait at kernel end
    asm volatile("barrier.cluster.arrive.aligned;" ::: "memory");

    // ---- P3: dense output for my 64 rows; __stcs streaming stores
    const float scale = 0.5f * __ldg(ncs + p);
    const float4 cT = *(const float4*)(colT + 4 * lane);
    const uint4 smv = srcm4[p * 32 + lane];
    const float m0 = (smv.x != 0u) ? 1.f : 0.f;
    const float m1 = (smv.y != 0u) ? 1.f : 0.f;
    const float m2 = (smv.z != 0u) ? 1.f : 0.f;
    const float m3 = (smv.w != 0u) ? 1.f : 0.f;

    const float4* tp  = (const float4*)tile + (tid >> 5) * 33 + lane;
    const float2* rip = rowInfo + (tid >> 5);
    float4* sco = out4 + (size_t)p * 4096 + half * 2048 + tid;
    float4* cor = sco + (size_t)PP * 4096;

    if (write_corr) {
        #pragma unroll
        for (int k = 0; k < 8; k++) {
            float2 ri = rip[8 * k];             // warp-uniform (rowTx, refmaskF)
            float4 x  = tp[k * 8 * 33];

            bool ax = x.x >= ri.x, bx = x.x >= cT.x;
            bool ay = x.y >= ri.x, by = x.y >= cT.y;
            bool az = x.z >= ri.x, bz = x.z >= cT.z;
            bool aw = x.w >= ri.x, bw = x.w >= cT.w;

            float svx = scale * __expf(x.x), svy = scale * __expf(x.y);
            float svz = scale * __expf(x.z), svw = scale * __expf(x.w);

            float4 s4;
            s4.x = (ax ? svx : 0.f) + (bx ? svx : 0.f);
            s4.y = (ay ? svy : 0.f) + (by ? svy : 0.f);
            s4.z = (az ? svz : 0.f) + (bz ? svz : 0.f);
            s4.w = (aw ? svw : 0.f) + (bw ? svw : 0.f);
            __stcs(sco + k * NT, s4);

            float4 c4;
            c4.x = ((ax || bx) && x.x > XTHRESH) ? ri.y * m0 : 0.f;
            c4.y = ((ay || by) && x.y > XTHRESH) ? ri.y * m1 : 0.f;
            c4.z = ((az || bz) && x.z > XTHRESH) ? ri.y * m2 : 0.f;
            c4.w = ((aw || bw) && x.w > XTHRESH) ? ri.y * m3 : 0.f;
            __stcs(cor + k * NT, c4);
        }
    } else {
        #pragma unroll
        for (int k = 0; k < 8; k++) {
            float2 ri = rip[8 * k];
            float4 x  = tp[k * 8 * 33];
            bool ax = x.x >= ri.x, bx = x.x >= cT.x;
            bool ay = x.y >= ri.x, by = x.y >= cT.y;
            bool az = x.z >= ri.x, bz = x.z >= cT.z;
            bool aw = x.w >= ri.x, bw = x.w >= cT.w;
            float svx = scale * __expf(x.x), svy = scale * __expf(x.y);
            float svz = scale * __expf(x.z), svw = scale * __expf(x.w);
            float4 s4;
            s4.x = (ax ? svx : 0.f) + (bx ? svx : 0.f);
            s4.y = (ay ? svy : 0.f) + (by ? svy : 0.f);
            s4.z = (az ? svz : 0.f) + (bz ? svz : 0.f);
            s4.w = (aw ? svw : 0.f) + (bw ? svw : 0.f);
            __stcs(sco + k * NT, s4);
        }
    }

    // don't exit while peer may still read my cp arrays
    asm volatile("barrier.cluster.wait.aligned;" ::: "memory");
}

extern "C" void kernel_launch(void* const* d_in, const int* in_sizes, int n_in,
                              void* d_out, int out_size) {
    const float4* msm4       = (const float4*)d_in[0];
    const unsigned int* refm = (const unsigned int*)d_in[1];
    const uint4* srcm4       = (const uint4*)d_in[2];
    const float* ncs         = (const float*)d_in[3];
    float4* out4             = (float4*)d_out;

    const int prs = PP * 128 * 128;
    int write_corr = (out_size >= 2 * prs) ? 1 : 0;

    fine_matching_kernel<<<2 * PP, NT>>>(msm4, refm, srcm4, ncs, out4,
                                         write_corr);
}

// round 14
// speedup vs baseline: 1.2140x; 1.0171x over previous
#include <cuda_runtime.h>
#include <cuda_bf16.h>
#include <cstdint>

// FineMatching (P=512, R=S=128, K=3, THRESH=0.05, OR-combine, conditional).
// R14 = R9 (best structure) + post-barrier latency fix:
//   srcm / ncs / refm prefetched in P0 (overlapping the cp.async tile fill),
//   parked in smem; P3 reads them via LDS (~30cyc) instead of issuing fresh
//   LDGs (~600cyc) right after the chip-wide cluster-barrier alignment point.
//   Zero extra live registers across P2; smem 36.9KB -> still 6 CTAs/SM.
// Structure: 2-CTA clusters, half-proposal (64x128) per CTA, cp.async fill,
// 4-accumulator raw-x scans, DSMEM col-partial exchange, __stcs stores.

#define PP 512
#define NT 256
#define XTHRESH (-2.99573227355f)   // ln(0.05)

struct Top3 { float v1, v2, v3; };

__device__ __forceinline__ void ins3(Top3& t, float v) {
    float t1 = fminf(t.v1, v);
    float t2 = fminf(t.v2, v);
    t.v1 = fmaxf(t.v1, v);
    t.v2 = fmaxf(t.v2, t1);
    t.v3 = fmaxf(t.v3, t2);
}

__device__ __forceinline__ void merge(Top3& a, const Top3& b) {
    ins3(a, b.v1);
    ins3(a, b.v2);
    ins3(a, b.v3);
}

__device__ __forceinline__ void merge_xor1(Top3& t) {
    Top3 b;
    b.v1 = __shfl_xor_sync(0xffffffffu, t.v1, 1);
    b.v2 = __shfl_xor_sync(0xffffffffu, t.v2, 1);
    b.v3 = __shfl_xor_sync(0xffffffffu, t.v3, 1);
    merge(t, b);
}

#define T3INIT {-1e30f, -1e30f, -1e30f}

__device__ __forceinline__ float ld_peer_f32(uint32_t local_saddr, uint32_t peer_rank) {
    uint32_t ra;
    float v;
    asm volatile("mapa.shared::cluster.u32 %0, %1, %2;"
                 : "=r"(ra) : "r"(local_saddr), "r"(peer_rank));
    asm volatile("ld.shared::cluster.f32 %0, [%1];" : "=f"(v) : "r"(ra));
    return v;
}

__global__ __launch_bounds__(NT, 6) __cluster_dims__(2, 1, 1)
void fine_matching_kernel(
    const float4* __restrict__ msm4,        // [P,R,S] as float4 (raw log-scores)
    const unsigned int* __restrict__ refm,  // [P,R] 32-bit bool
    const unsigned int* __restrict__ srcm,  // [P,S] 32-bit bool
    const float* __restrict__ ncs,          // [P]
    float4* __restrict__ out4,              // [score | corr] as float4
    int write_corr)
{
    __shared__ __align__(16) float tile[64 * 132];   // half-tile, pitch 132
    __shared__ float cp1[128], cp2[128], cp3[128];   // my col partial top-3
    __shared__ __align__(16) float colT[128];        // merged col thresholds
    __shared__ __align__(16) float smF[128];         // src mask as 0/1 float
    __shared__ float ncsS;                           // 0.5 * ncs[p]
    __shared__ float2 rowInfo[64];                   // (rowTx, refmaskF)

    const int bid  = blockIdx.x;
    const int p    = bid >> 1;
    const int half = bid & 1;                        // == cluster rank
    const uint32_t peer = (uint32_t)(half ^ 1);
    const int tid  = threadIdx.x;
    const int lane = tid & 31;

    // ---- P0a: issue small prefetches (overlap with cp.async fill below)
    float pf = 0.0f;
    if (tid < 64)        pf = (refm[p * 128 + half * 64 + tid] != 0u) ? 1.0f : 0.0f;
    else if (tid < 192)  pf = (srcm[p * 128 + (tid - 64)] != 0u) ? 1.0f : 0.0f;
    else if (tid == 192) pf = 0.5f * ncs[p];

    // ---- P1: half-tile fill via cp.async (8 x 16B in flight)
    {
        const float4* g = msm4 + p * 4096 + half * 2048 + tid;
        uint32_t sp = (uint32_t)__cvta_generic_to_shared(
            (float4*)tile + (tid >> 5) * 33 + lane);
        #pragma unroll
        for (int k = 0; k < 8; k++) {
            asm volatile("cp.async.cg.shared.global [%0], [%1], 16;"
                         :: "r"(sp + k * (8 * 33 * 16)), "l"(g + k * NT));
        }
        asm volatile("cp.async.commit_group;");
    }

    // ---- P0b: park prefetched scalars in smem
    if (tid < 64)        rowInfo[tid].y = pf;
    else if (tid < 192)  smF[tid - 64] = pf;
    else if (tid == 192) ncsS = pf;

    asm volatile("cp.async.wait_group 0;" ::: "memory");
    __syncthreads();

    // ---- P2: local scans (threads 0..127 cols, 128..255 rows)
    if (tid < 128) {
        // 1 thread per column, 64 rows, 4 interleaved accumulators
        const float* base = tile + tid;
        Top3 t0 = T3INIT, t1 = T3INIT, t2 = T3INIT, t3 = T3INIT;
        #pragma unroll
        for (int j = 0; j < 16; j++) {
            ins3(t0, base[(4 * j + 0) * 132]);
            ins3(t1, base[(4 * j + 1) * 132]);
            ins3(t2, base[(4 * j + 2) * 132]);
            ins3(t3, base[(4 * j + 3) * 132]);
        }
        merge(t0, t1);
        merge(t2, t3);
        merge(t0, t2);
        cp1[tid] = t0.v1;
        cp2[tid] = t0.v2;
        cp3[tid] = t0.v3;
    } else {
        // 2 threads per row (64 rows), LDS.128; half1 f4 20..31 then 16..19
        const int u  = tid - 128;
        const int r  = u >> 1;
        const int hf = u & 1;
        Top3 t0 = T3INIT, t1 = T3INIT, t2 = T3INIT, t3 = T3INIT;
        const float4* ra = (const float4*)tile + r * 33 + (hf ? 20 : 0);
        #pragma unroll
        for (int j = 0; j < 12; j++) {
            float4 v = ra[j];
            ins3(t0, v.x);
            ins3(t1, v.y);
            ins3(t2, v.z);
            ins3(t3, v.w);
        }
        const float4* rb = (const float4*)tile + r * 33 + (hf ? 16 : 12);
        #pragma unroll
        for (int j = 0; j < 4; j++) {
            float4 v = rb[j];
            ins3(t0, v.x);
            ins3(t1, v.y);
            ins3(t2, v.z);
            ins3(t3, v.w);
        }
        merge(t0, t1);
        merge(t2, t3);
        merge(t0, t2);
        merge_xor1(t0);
        if (!hf) rowInfo[r].x = t0.v3;
    }
    __syncthreads();

    // ---- Exchange col partials with cluster peer, merge
    asm volatile("barrier.cluster.arrive.aligned;" ::: "memory");
    asm volatile("barrier.cluster.wait.aligned;" ::: "memory");

    if (tid < 128) {
        Top3 t;
        t.v1 = cp1[tid];
        t.v2 = cp2[tid];
        t.v3 = cp3[tid];
        uint32_t a1 = (uint32_t)__cvta_generic_to_shared(cp1 + tid);
        uint32_t a2 = (uint32_t)__cvta_generic_to_shared(cp2 + tid);
        uint32_t a3 = (uint32_t)__cvta_generic_to_shared(cp3 + tid);
        ins3(t, ld_peer_f32(a1, peer));
        ins3(t, ld_peer_f32(a2, peer));
        ins3(t, ld_peer_f32(a3, peer));
        colT[tid] = t.v3;
    }
    __syncthreads();
    // done touching peer smem after this point; arrive now, wait at kernel end
    asm volatile("barrier.cluster.arrive.aligned;" ::: "memory");

    // ---- P3: dense output; all scalars from smem (LDS), __stcs stores
    const float scale = ncsS;
    const float4 cT = *(const float4*)(colT + 4 * lane);
    const float4 m4 = *(const float4*)(smF + 4 * lane);

    const float4* tp  = (const float4*)tile + (tid >> 5) * 33 + lane;
    const float2* rip = rowInfo + (tid >> 5);
    float4* sco = out4 + (size_t)p * 4096 + half * 2048 + tid;
    float4* cor = sco + (size_t)PP * 4096;

    if (write_corr) {
        #pragma unroll
        for (int k = 0; k < 8; k++) {
            float2 ri = rip[8 * k];             // warp-uniform (rowTx, refmaskF)
            float4 x  = tp[k * 8 * 33];

            bool ax = x.x >= ri.x, bx = x.x >= cT.x;
            bool ay = x.y >= ri.x, by = x.y >= cT.y;
            bool az = x.z >= ri.x, bz = x.z >= cT.z;
            bool aw = x.w >= ri.x, bw = x.w >= cT.w;

            float svx = scale * __expf(x.x), svy = scale * __expf(x.y);
            float svz = scale * __expf(x.z), svw = scale * __expf(x.w);

            float4 s4;
            s4.x = (ax ? svx : 0.f) + (bx ? svx : 0.f);
            s4.y = (ay ? svy : 0.f) + (by ? svy : 0.f);
            s4.z = (az ? svz : 0.f) + (bz ? svz : 0.f);
            s4.w = (aw ? svw : 0.f) + (bw ? svw : 0.f);
            __stcs(sco + k * NT, s4);

            float4 c4;
            c4.x = ((ax || bx) && x.x > XTHRESH) ? ri.y * m4.x : 0.f;
            c4.y = ((ay || by) && x.y > XTHRESH) ? ri.y * m4.y : 0.f;
            c4.z = ((az || bz) && x.z > XTHRESH) ? ri.y * m4.z : 0.f;
            c4.w = ((aw || bw) && x.w > XTHRESH) ? ri.y * m4.w : 0.f;
            __stcs(cor + k * NT, c4);
        }
    } else {
        #pragma unroll
        for (int k = 0; k < 8; k++) {
            float2 ri = rip[8 * k];
            float4 x  = tp[k * 8 * 33];
            bool ax = x.x >= ri.x, bx = x.x >= cT.x;
            bool ay = x.y >= ri.x, by = x.y >= cT.y;
            bool az = x.z >= ri.x, bz = x.z >= cT.z;
            bool aw = x.w >= ri.x, bw = x.w >= cT.w;
            float svx = scale * __expf(x.x), svy = scale * __expf(x.y);
            float svz = scale * __expf(x.z), svw = scale * __expf(x.w);
            float4 s4;
            s4.x = (ax ? svx : 0.f) + (bx ? svx : 0.f);
            s4.y = (ay ? svy : 0.f) + (by ? svy : 0.f);
            s4.z = (az ? svz : 0.f) + (bz ? svz : 0.f);
            s4.w = (aw ? svw : 0.f) + (bw ? svw : 0.f);
            __stcs(sco + k * NT, s4);
        }
    }

    // don't exit while peer may still read my cp arrays
    asm volatile("barrier.cluster.wait.aligned;" ::: "memory");
}

extern "C" void kernel_launch(void* const* d_in, const int* in_sizes, int n_in,
                              void* d_out, int out_size) {
    const float4* msm4       = (const float4*)d_in[0];
    const unsigned int* refm = (const unsigned int*)d_in[1];
    const unsigned int* srcm = (const unsigned int*)d_in[2];
    const float* ncs         = (const float*)d_in[3];
    float4* out4             = (float4*)d_out;

    const int prs = PP * 128 * 128;
    int write_corr = (out_size >= 2 * prs) ? 1 : 0;

    fine_matching_kernel<<<2 * PP, NT>>>(msm4, refm, srcm, ncs, out4,
                                         write_corr);
}